// round 4
// baseline (speedup 1.0000x reference)
#include <cuda_runtime.h>
#include <cstdint>

#define NUM_C 1000
#define DIM 128
#define MSZ 64
#define BATCH 64
#define LEN 512

// ---------------- device scratch (static, no runtime alloc) ----------------
__device__ __align__(16) float g_W [NUM_C * MSZ];     // softmax(Ek@Mk^T) per q
__device__ __align__(16) float g_Ee[2 * NUM_C * DIM]; // sigmoid(Ev@We+be) per x
__device__ __align__(16) float g_Ea[2 * NUM_C * DIM]; // tanh(Ev@Wa+ba) per x
__device__ __align__(16) float g_Kf[NUM_C * DIM];     // Ek @ Wf[128:256,:]
__device__ __align__(16) float g_read[BATCH * LEN * DIM];

// ---------------- packed f32x2 helpers ----------------
__device__ __forceinline__ void fma2(unsigned long long& d,
                                     unsigned long long a,
                                     unsigned long long b,
                                     unsigned long long c) {
    asm("fma.rn.f32x2 %0, %1, %2, %3;" : "=l"(d) : "l"(a), "l"(b), "l"(c));
}
__device__ __forceinline__ unsigned long long pack2(float lo, float hi) {
    unsigned long long r;
    asm("mov.b64 %0, {%1, %2};" : "=l"(r) : "f"(lo), "f"(hi));
    return r;
}
__device__ __forceinline__ void unpack2(unsigned long long v, float& lo, float& hi) {
    asm("mov.b64 {%0, %1}, %2;" : "=f"(lo), "=f"(hi) : "l"(v));
}
__device__ __forceinline__ float sum2(unsigned long long v) {
    float lo, hi;
    asm("mov.b64 {%0, %1}, %2;" : "=f"(lo), "=f"(hi) : "l"(v));
    return lo + hi;
}

// ============================================================================
// P: fused precompute.  grid = 500, block = 256.
//    blocks [0,250):   erase/add tables, 8 Ev-rows each.
//                      threads 0-127 erase (We), 128-255 add (Wa).
//                      rows packed as f32x2 -> 4 fma2 per j per thread.
//    blocks [250,500): softmax weights + Kf, 4 Ek-rows each.
//                      threads 0-127 Kf, threads 128-255 logits+softmax.
// ============================================================================
__global__ __launch_bounds__(256)
void k_pre(const float* __restrict__ Ev,
           const float* __restrict__ We, const float* __restrict__ be,
           const float* __restrict__ Wa, const float* __restrict__ ba,
           const float* __restrict__ Ek,
           const float* __restrict__ Mk,
           const float* __restrict__ Wf) {
    int t = threadIdx.x;

    if (blockIdx.x < 250) {
        // ------- erase/add branch: rows row0..row0+7 -------
        __shared__ __align__(16) float vt[DIM][8];   // [j][row] transposed
        int row0 = blockIdx.x * 8;
#pragma unroll
        for (int k = 0; k < 4; k++) {
            int idx = t + k * 256;          // 1024 elements
            int i = idx >> 7, c = idx & 127;
            vt[c][i] = Ev[(row0 + i) * DIM + c];
        }
        __syncthreads();

        int half = t >> 7;                  // 0 = erase, 1 = add
        int col  = t & 127;
        const float* W_ = half ? Wa : We;
        float bias = half ? ba[col] : be[col];
        unsigned long long acc2[4];
        unsigned long long b2 = pack2(bias, bias);
#pragma unroll
        for (int p = 0; p < 4; p++) acc2[p] = b2;

#pragma unroll 4
        for (int j = 0; j < DIM; j++) {
            float w = W_[j * DIM + col];
            unsigned long long w2 = pack2(w, w);
            const unsigned long long* vp = (const unsigned long long*)&vt[j][0];
#pragma unroll
            for (int p = 0; p < 4; p++)
                fma2(acc2[p], vp[p], w2, acc2[p]);
        }

        float* dst = half ? g_Ea : g_Ee;
#pragma unroll
        for (int p = 0; p < 4; p++) {
            float lo, hi;
            unpack2(acc2[p], lo, hi);
            if (half) {
                dst[(row0 + 2 * p)     * DIM + col] = tanhf(lo);
                dst[(row0 + 2 * p + 1) * DIM + col] = tanhf(hi);
            } else {
                dst[(row0 + 2 * p)     * DIM + col] = 1.0f / (1.0f + expf(-lo));
                dst[(row0 + 2 * p + 1) * DIM + col] = 1.0f / (1.0f + expf(-hi));
            }
        }
    } else {
        // ------- w/Kf branch: rows row0..row0+3 -------
        __shared__ float krows[4][DIM];
        __shared__ float lg[4][MSZ];
        int row0 = (blockIdx.x - 250) * 4;
#pragma unroll
        for (int k = 0; k < 2; k++) {
            int idx = t + k * 256;          // 512 elements
            int i = idx >> 7, c = idx & 127;
            krows[i][c] = Ek[(row0 + i) * DIM + c];
        }
        __syncthreads();

        if (t < 128) {
            // Kf columns: 4 rows per weight element
            float acc[4] = {0.f, 0.f, 0.f, 0.f};
#pragma unroll 4
            for (int j = 0; j < DIM; j++) {
                float wf = Wf[(DIM + j) * DIM + t];
#pragma unroll
                for (int i = 0; i < 4; i++)
                    acc[i] = fmaf(krows[i][j], wf, acc[i]);
            }
#pragma unroll
            for (int i = 0; i < 4; i++)
                g_Kf[(row0 + i) * DIM + t] = acc[i];
        } else {
            // logits: 2 threads per memory slot (split j in halves)
            int lt = t - 128;
            int m = lt >> 1, jh = lt & 1;
            float la[4] = {0.f, 0.f, 0.f, 0.f};
            const float* mkp = Mk + m * DIM + jh * 64;
#pragma unroll 4
            for (int j = 0; j < 64; j++) {
                float mk = mkp[j];
#pragma unroll
                for (int i = 0; i < 4; i++)
                    la[i] = fmaf(krows[i][jh * 64 + j], mk, la[i]);
            }
#pragma unroll
            for (int i = 0; i < 4; i++) {
                la[i] += __shfl_xor_sync(0xFFFFFFFFu, la[i], 1);
                if (jh == 0) lg[i][m] = la[i];
            }
        }
        __syncthreads();

        if (t >= 128) {
            // softmax: one warp per row, 2 slots per lane
            int lt = t - 128;
            int i = lt >> 5, l = lt & 31;
            float v0 = lg[i][l], v1 = lg[i][l + 32];
            float mx = fmaxf(v0, v1);
#pragma unroll
            for (int off = 1; off < 32; off <<= 1)
                mx = fmaxf(mx, __shfl_xor_sync(0xFFFFFFFFu, mx, off));
            float e0 = expf(v0 - mx), e1 = expf(v1 - mx);
            float s = e0 + e1;
#pragma unroll
            for (int off = 1; off < 32; off <<= 1)
                s += __shfl_xor_sync(0xFFFFFFFFu, s, off);
            float inv = 1.0f / s;
            g_W[(row0 + i) * MSZ + l]      = e0 * inv;
            g_W[(row0 + i) * MSZ + l + 32] = e1 * inv;
        }
    }
}

// ============================================================================
// S: sequential memory scan.  grid = (2, 64), block = 256
//    3 packed FMA per element: Mv += w*(a - e*Mv);  read += w*Mv_old
//    Register-staged prefetch of next 16-step chunk overlaps compute.
// ============================================================================
__global__ __launch_bounds__(256)
void k_scan(const int* __restrict__ q, const int* __restrict__ r,
            const float* __restrict__ Mv0) {
    int b = blockIdx.y;
    int dsplit = blockIdx.x;
    int tid = threadIdx.x;
    int dl = tid >> 2;        // 0..63
    int mg = tid & 3;         // 0..3
    int d = dsplit * 64 + dl;
    int m0 = mg * 16;

    __shared__ int sq[LEN];
    __shared__ int sx[LEN];
    __shared__ __align__(16) float sh_w[16][MSZ];
    __shared__ float sh_e[16][64];
    __shared__ float sh_a[16][64];

    {
        const int* qb = q + b * LEN;
        const int* rb = r + b * LEN;
        for (int i = tid; i < LEN; i += 256) {
            int qv = qb[i];
            sq[i] = qv;
            sx[i] = qv + NUM_C * rb[i];
        }
    }

    unsigned long long Mv[8];
#pragma unroll
    for (int i = 0; i < 8; i++) {
        float lo = Mv0[(m0 + 2 * i) * DIM + d];
        float hi = Mv0[(m0 + 2 * i + 1) * DIM + d];
        Mv[i] = pack2(lo, hi);
    }
    __syncthreads();

    float rw[4], re[4], ra[4];
    int ws0[4], wm[4], es0[4], ed[4];
#pragma unroll
    for (int k = 0; k < 4; k++) {
        int idx = tid + k * 256;
        ws0[k] = idx >> 6; wm[k] = idx & 63;
        es0[k] = idx >> 6; ed[k] = (idx & 63) + dsplit * 64;
    }
#pragma unroll
    for (int k = 0; k < 4; k++) {
        rw[k] = g_W [sq[ws0[k]] * MSZ + wm[k]];
        re[k] = g_Ee[sx[es0[k]] * DIM + ed[k]];
        ra[k] = g_Ea[sx[es0[k]] * DIM + ed[k]];
    }

    for (int c = 0; c < LEN / 16; c++) {
#pragma unroll
        for (int k = 0; k < 4; k++) {
            sh_w[ws0[k]][wm[k]]      = rw[k];
            sh_e[es0[k]][ed[k] & 63] = re[k];
            sh_a[es0[k]][ed[k] & 63] = ra[k];
        }
        __syncthreads();

        if (c < LEN / 16 - 1) {
            int t1 = (c + 1) * 16;
#pragma unroll
            for (int k = 0; k < 4; k++) {
                rw[k] = g_W [sq[t1 + ws0[k]] * MSZ + wm[k]];
                re[k] = g_Ee[sx[t1 + es0[k]] * DIM + ed[k]];
                ra[k] = g_Ea[sx[t1 + es0[k]] * DIM + ed[k]];
            }
        }

        int t0 = c * 16;
#pragma unroll 4
        for (int s = 0; s < 16; s++) {
            float e = sh_e[s][dl];
            float a = sh_a[s][dl];
            unsigned long long ne2 = pack2(-e, -e);
            unsigned long long a2  = pack2(a, a);
            unsigned long long rd = 0ull;
            const unsigned long long* wrow =
                (const unsigned long long*)(&sh_w[s][m0]);
#pragma unroll
            for (int i = 0; i < 8; i++) {
                unsigned long long w2 = wrow[i];
                unsigned long long tmp;
                fma2(rd, w2, Mv[i], rd);       // read += w * Mv_old
                fma2(tmp, ne2, Mv[i], a2);     // tmp = a - e*Mv
                fma2(Mv[i], w2, tmp, Mv[i]);   // Mv += w*tmp
            }
            float rs = sum2(rd);
            rs += __shfl_xor_sync(0xFFFFFFFFu, rs, 1);
            rs += __shfl_xor_sync(0xFFFFFFFFu, rs, 2);
            if (mg == 0)
                g_read[(b * LEN + t0 + s) * DIM + d] = rs;
        }
        __syncthreads();
    }
}

// ============================================================================
// F: tiled SGEMM  f = tanh(read@Wf_r + Kf[q] + bf); p = sigmoid(f@Wp + bp)
//    grid = 256 (128 tokens each), block = 256, 8x8 thread tile,
//    n-dim packed f32x2 accumulators, Wf_r resident in 64KB shared.
// ============================================================================
__global__ __launch_bounds__(256, 2)
void k_final(const int* __restrict__ q,
             const float* __restrict__ Wf,
             const float* __restrict__ bf,
             const float* __restrict__ Wp,
             const float* __restrict__ bp,
             float* __restrict__ out) {
    __shared__ __align__(16) float Wfs[DIM][DIM];  // 64 KB: [k][n]
    __shared__ float rds[128][20];                 // read tile [token][k]
    __shared__ float part[128][17];                // per-token partial sums

    int tid = threadIdx.x;
    int ty = tid >> 4, tx = tid & 15;
    int tok0 = blockIdx.x * 128;

#pragma unroll
    for (int i = 0; i < 16; i++) {
        int idx = (tid + i * 256) * 4;
        *(float4*)&Wfs[idx >> 7][idx & 127] = *(const float4*)&Wf[idx];
    }
    __syncthreads();

    unsigned long long acc2[8][4];
#pragma unroll
    for (int i = 0; i < 8; i++)
#pragma unroll
        for (int j = 0; j < 4; j++) acc2[i][j] = 0ull;

    for (int kt = 0; kt < 8; kt++) {
#pragma unroll
        for (int v = 0; v < 2; v++) {
            int f = tid * 2 + v;
            int tok = f >> 2, dpos = (f & 3) * 4;
            *(float4*)&rds[tok][dpos] =
                *(const float4*)&g_read[(tok0 + tok) * DIM + kt * 16 + dpos];
        }
        __syncthreads();

#pragma unroll
        for (int kk = 0; kk < 16; kk++) {
            float av[8];
#pragma unroll
            for (int i = 0; i < 8; i++) av[i] = rds[ty * 8 + i][kk];
            float4 b0 = *(const float4*)&Wfs[kt * 16 + kk][tx * 8];
            float4 b1 = *(const float4*)&Wfs[kt * 16 + kk][tx * 8 + 4];
            unsigned long long bv2[4];
            bv2[0] = pack2(b0.x, b0.y);
            bv2[1] = pack2(b0.z, b0.w);
            bv2[2] = pack2(b1.x, b1.y);
            bv2[3] = pack2(b1.z, b1.w);
#pragma unroll
            for (int i = 0; i < 8; i++) {
                unsigned long long a2 = pack2(av[i], av[i]);
#pragma unroll
                for (int j = 0; j < 4; j++)
                    fma2(acc2[i][j], a2, bv2[j], acc2[i][j]);
            }
        }
        __syncthreads();
    }

    // epilogue
    float4 bf0 = *(const float4*)&bf[tx * 8];
    float4 bf1 = *(const float4*)&bf[tx * 8 + 4];
    float bfv[8] = {bf0.x, bf0.y, bf0.z, bf0.w, bf1.x, bf1.y, bf1.z, bf1.w};
    float4 wp0 = *(const float4*)&Wp[tx * 8];
    float4 wp1 = *(const float4*)&Wp[tx * 8 + 4];
    float wpv[8] = {wp0.x, wp0.y, wp0.z, wp0.w, wp1.x, wp1.y, wp1.z, wp1.w};

    int qv[8];
#pragma unroll
    for (int i = 0; i < 8; i++) qv[i] = q[tok0 + ty * 8 + i];

#pragma unroll
    for (int i = 0; i < 8; i++) {
        const float* kf = g_Kf + qv[i] * DIM + tx * 8;
        float psum = 0.0f;
#pragma unroll
        for (int j = 0; j < 4; j++) {
            float lo, hi;
            unpack2(acc2[i][j], lo, hi);
            float f0 = tanhf(lo + kf[2 * j]     + bfv[2 * j]);
            float f1 = tanhf(hi + kf[2 * j + 1] + bfv[2 * j + 1]);
            psum = fmaf(f0, wpv[2 * j], psum);
            psum = fmaf(f1, wpv[2 * j + 1], psum);
        }
        part[ty * 8 + i][tx] = psum;
    }
    __syncthreads();

    if (tid < 128) {
        float s = 0.0f;
#pragma unroll
        for (int x = 0; x < 16; x++) s += part[tid][x];
        out[tok0 + tid] = 1.0f / (1.0f + expf(-(s + bp[0])));
    }
}

// ============================================================================
extern "C" void kernel_launch(void* const* d_in, const int* in_sizes, int n_in,
                              void* d_out, int out_size) {
    const int*   q   = (const int*)  d_in[0];
    const int*   r   = (const int*)  d_in[1];
    const float* Ek  = (const float*)d_in[2];
    const float* Ev  = (const float*)d_in[3];
    const float* Mk  = (const float*)d_in[4];
    const float* Mv0 = (const float*)d_in[5];
    const float* We  = (const float*)d_in[6];
    const float* be  = (const float*)d_in[7];
    const float* Wa  = (const float*)d_in[8];
    const float* ba  = (const float*)d_in[9];
    const float* Wf  = (const float*)d_in[10];
    const float* bf  = (const float*)d_in[11];
    const float* Wp  = (const float*)d_in[12];
    const float* bp  = (const float*)d_in[13];
    float* out = (float*)d_out;

    k_pre<<<500, 256>>>(Ev, We, be, Wa, ba, Ek, Mk, Wf);
    dim3 gs(2, BATCH);
    k_scan<<<gs, 256>>>(q, r, Mv0);
    k_final<<<BATCH * LEN / 128, 256>>>(q, Wf, bf, Wp, bp, out);
}

// round 5
// speedup vs baseline: 1.0721x; 1.0721x over previous
#include <cuda_runtime.h>
#include <cstdint>

#define NUM_C 1000
#define DIM 128
#define MSZ 64
#define BATCH 64
#define LEN 512

// ---------------- device scratch (static, no runtime alloc) ----------------
__device__ __align__(16) float g_W [NUM_C * MSZ];     // softmax(Ek@Mk^T) per q
__device__ __align__(16) float g_Ee[2 * NUM_C * DIM]; // sigmoid(Ev@We+be) per x
__device__ __align__(16) float g_Ea[2 * NUM_C * DIM]; // tanh(Ev@Wa+ba) per x
__device__ __align__(16) float g_Kf[NUM_C * DIM];     // Ek @ Wf[128:256,:]
__device__ __align__(16) float g_read[BATCH * LEN * DIM];

// ---------------- packed f32x2 helpers ----------------
__device__ __forceinline__ void fma2(unsigned long long& d,
                                     unsigned long long a,
                                     unsigned long long b,
                                     unsigned long long c) {
    asm("fma.rn.f32x2 %0, %1, %2, %3;" : "=l"(d) : "l"(a), "l"(b), "l"(c));
}
__device__ __forceinline__ unsigned long long pack2(float lo, float hi) {
    unsigned long long r;
    asm("mov.b64 %0, {%1, %2};" : "=l"(r) : "f"(lo), "f"(hi));
    return r;
}
__device__ __forceinline__ void unpack2(unsigned long long v, float& lo, float& hi) {
    asm("mov.b64 {%0, %1}, %2;" : "=f"(lo), "=f"(hi) : "l"(v));
}
__device__ __forceinline__ float sum2(unsigned long long v) {
    float lo, hi;
    asm("mov.b64 {%0, %1}, %2;" : "=f"(lo), "=f"(hi) : "l"(v));
    return lo + hi;
}

// ============================================================================
// P: fused precompute.  grid = 375, block = 256.
//    blocks [0,250):   erase/add, 8 Ev-rows each; j-reduction split across
//                      thread halves, partials combined via shared.
//    blocks [250,375): softmax weights + Kf, 8 Ek-rows each; every thread
//                      does Kf (2-way j-split) AND logits (4-way j-split).
// ============================================================================
__global__ __launch_bounds__(256)
void k_pre(const float* __restrict__ Ev,
           const float* __restrict__ We, const float* __restrict__ be,
           const float* __restrict__ Wa, const float* __restrict__ ba,
           const float* __restrict__ Ek,
           const float* __restrict__ Mk,
           const float* __restrict__ Wf) {
    __shared__ float buf[12352];   // 48.25 KB, reused by both branches
    int t = threadIdx.x;

    if (blockIdx.x < 250) {
        // ---------------- erase/add branch: rows row0..row0+7 ----------------
        float (*vs)[DIM]  = (float (*)[DIM])buf;            // [8][128]
        float (*pse)[DIM] = (float (*)[DIM])(buf + 1024);   // [8][128]
        float (*psa)[DIM] = (float (*)[DIM])(buf + 2048);   // [8][128]
        int row0 = blockIdx.x * 8;
#pragma unroll
        for (int k = 0; k < 4; k++) {
            int idx = t + k * 256;
            vs[idx >> 7][idx & 127] = Ev[row0 * DIM + idx];
        }
        __syncthreads();

        int col = t & 127, jh = t >> 7;
        int j0 = jh * 64;
        float ae[8] = {0,0,0,0,0,0,0,0};
        float aa[8] = {0,0,0,0,0,0,0,0};
#pragma unroll 4
        for (int jj = 0; jj < 64; jj++) {
            int j = j0 + jj;
            float we = We[j * DIM + col];
            float wa = Wa[j * DIM + col];
#pragma unroll
            for (int i = 0; i < 8; i++) {
                float v = vs[i][j];
                ae[i] = fmaf(v, we, ae[i]);
                aa[i] = fmaf(v, wa, aa[i]);
            }
        }
        // cross-half exchange: jh=0 exports aa, jh=1 exports ae
        if (jh == 0) {
#pragma unroll
            for (int i = 0; i < 8; i++) psa[i][col] = aa[i];
        } else {
#pragma unroll
            for (int i = 0; i < 8; i++) pse[i][col] = ae[i];
        }
        __syncthreads();
        if (jh == 0) {
            float bev = be[col];
#pragma unroll
            for (int i = 0; i < 8; i++) {
                float s = ae[i] + pse[i][col] + bev;
                g_Ee[(row0 + i) * DIM + col] = 1.0f / (1.0f + expf(-s));
            }
        } else {
            float bav = ba[col];
#pragma unroll
            for (int i = 0; i < 8; i++) {
                float s = aa[i] + psa[i][col] + bav;
                g_Ea[(row0 + i) * DIM + col] = tanhf(s);
            }
        }
    } else {
        // ---------------- w/Kf branch: rows row0..row0+7 ----------------
        float (*Mks)[129]   = (float (*)[129])buf;                  // 8256
        float (*krows)[DIM] = (float (*)[DIM])(buf + 8256);         // 1024
        float (*lgp)[8][MSZ] = (float (*)[8][MSZ])(buf + 9280);     // 1536
        float (*lg)[MSZ]    = (float (*)[MSZ])(buf + 10816);        // 512
        float (*psk)[DIM]   = (float (*)[DIM])(buf + 11328);        // 1024
        int row0 = (blockIdx.x - 250) * 8;
#pragma unroll
        for (int k = 0; k < 4; k++) {
            int idx = t + k * 256;
            krows[idx >> 7][idx & 127] = Ek[row0 * DIM + idx];
        }
#pragma unroll 8
        for (int k = 0; k < 32; k++) {
            int idx = t + k * 256;
            Mks[idx >> 7][idx & 127] = Mk[idx];
        }
        __syncthreads();

        // Kf: 2-way j-split
        int col = t & 127, jh = t >> 7;
        float ak[8] = {0,0,0,0,0,0,0,0};
#pragma unroll 4
        for (int jj = 0; jj < 64; jj++) {
            int j = jh * 64 + jj;
            float wf = Wf[(DIM + j) * DIM + col];
#pragma unroll
            for (int i = 0; i < 8; i++)
                ak[i] = fmaf(krows[i][j], wf, ak[i]);
        }
        if (jh == 1) {
#pragma unroll
            for (int i = 0; i < 8; i++) psk[i][col] = ak[i];
        }

        // logits: 4-way j-split, slot m = t & 63
        int m = t & 63, gh = t >> 6;
        float la[8] = {0,0,0,0,0,0,0,0};
#pragma unroll 4
        for (int jj = 0; jj < 32; jj++) {
            int j = gh * 32 + jj;
            float mk = Mks[m][j];
#pragma unroll
            for (int i = 0; i < 8; i++)
                la[i] = fmaf(krows[i][j], mk, la[i]);
        }
        if (gh > 0) {
#pragma unroll
            for (int i = 0; i < 8; i++) lgp[gh - 1][i][m] = la[i];
        }
        __syncthreads();

        if (jh == 0) {
#pragma unroll
            for (int i = 0; i < 8; i++)
                g_Kf[(row0 + i) * DIM + col] = ak[i] + psk[i][col];
        }
        if (gh == 0) {
#pragma unroll
            for (int i = 0; i < 8; i++)
                lg[i][m] = la[i] + lgp[0][i][m] + lgp[1][i][m] + lgp[2][i][m];
        }
        __syncthreads();

        // softmax: one warp per row, 2 slots per lane
        int row = t >> 5, l = t & 31;
        float v0 = lg[row][l], v1 = lg[row][l + 32];
        float mx = fmaxf(v0, v1);
#pragma unroll
        for (int off = 1; off < 32; off <<= 1)
            mx = fmaxf(mx, __shfl_xor_sync(0xFFFFFFFFu, mx, off));
        float e0 = expf(v0 - mx), e1 = expf(v1 - mx);
        float s = e0 + e1;
#pragma unroll
        for (int off = 1; off < 32; off <<= 1)
            s += __shfl_xor_sync(0xFFFFFFFFu, s, off);
        float inv = 1.0f / s;
        g_W[(row0 + row) * MSZ + l]      = e0 * inv;
        g_W[(row0 + row) * MSZ + l + 32] = e1 * inv;
    }
}

// ============================================================================
// S: sequential memory scan.  grid = (2, 64), block = 256  (unchanged)
// ============================================================================
__global__ __launch_bounds__(256)
void k_scan(const int* __restrict__ q, const int* __restrict__ r,
            const float* __restrict__ Mv0) {
    int b = blockIdx.y;
    int dsplit = blockIdx.x;
    int tid = threadIdx.x;
    int dl = tid >> 2;        // 0..63
    int mg = tid & 3;         // 0..3
    int d = dsplit * 64 + dl;
    int m0 = mg * 16;

    __shared__ int sq[LEN];
    __shared__ int sx[LEN];
    __shared__ __align__(16) float sh_w[16][MSZ];
    __shared__ float sh_e[16][64];
    __shared__ float sh_a[16][64];

    {
        const int* qb = q + b * LEN;
        const int* rb = r + b * LEN;
        for (int i = tid; i < LEN; i += 256) {
            int qv = qb[i];
            sq[i] = qv;
            sx[i] = qv + NUM_C * rb[i];
        }
    }

    unsigned long long Mv[8];
#pragma unroll
    for (int i = 0; i < 8; i++) {
        float lo = Mv0[(m0 + 2 * i) * DIM + d];
        float hi = Mv0[(m0 + 2 * i + 1) * DIM + d];
        Mv[i] = pack2(lo, hi);
    }
    __syncthreads();

    float rw[4], re[4], ra[4];
    int ws0[4], wm[4], es0[4], ed[4];
#pragma unroll
    for (int k = 0; k < 4; k++) {
        int idx = tid + k * 256;
        ws0[k] = idx >> 6; wm[k] = idx & 63;
        es0[k] = idx >> 6; ed[k] = (idx & 63) + dsplit * 64;
    }
#pragma unroll
    for (int k = 0; k < 4; k++) {
        rw[k] = g_W [sq[ws0[k]] * MSZ + wm[k]];
        re[k] = g_Ee[sx[es0[k]] * DIM + ed[k]];
        ra[k] = g_Ea[sx[es0[k]] * DIM + ed[k]];
    }

    for (int c = 0; c < LEN / 16; c++) {
#pragma unroll
        for (int k = 0; k < 4; k++) {
            sh_w[ws0[k]][wm[k]]      = rw[k];
            sh_e[es0[k]][ed[k] & 63] = re[k];
            sh_a[es0[k]][ed[k] & 63] = ra[k];
        }
        __syncthreads();

        if (c < LEN / 16 - 1) {
            int t1 = (c + 1) * 16;
#pragma unroll
            for (int k = 0; k < 4; k++) {
                rw[k] = g_W [sq[t1 + ws0[k]] * MSZ + wm[k]];
                re[k] = g_Ee[sx[t1 + es0[k]] * DIM + ed[k]];
                ra[k] = g_Ea[sx[t1 + es0[k]] * DIM + ed[k]];
            }
        }

        int t0 = c * 16;
#pragma unroll 4
        for (int s = 0; s < 16; s++) {
            float e = sh_e[s][dl];
            float a = sh_a[s][dl];
            unsigned long long ne2 = pack2(-e, -e);
            unsigned long long a2  = pack2(a, a);
            unsigned long long rd = 0ull;
            const unsigned long long* wrow =
                (const unsigned long long*)(&sh_w[s][m0]);
#pragma unroll
            for (int i = 0; i < 8; i++) {
                unsigned long long w2 = wrow[i];
                unsigned long long tmp;
                fma2(rd, w2, Mv[i], rd);       // read += w * Mv_old
                fma2(tmp, ne2, Mv[i], a2);     // tmp = a - e*Mv
                fma2(Mv[i], w2, tmp, Mv[i]);   // Mv += w*tmp
            }
            float rs = sum2(rd);
            rs += __shfl_xor_sync(0xFFFFFFFFu, rs, 1);
            rs += __shfl_xor_sync(0xFFFFFFFFu, rs, 2);
            if (mg == 0)
                g_read[(b * LEN + t0 + s) * DIM + d] = rs;
        }
        __syncthreads();
    }
}

// ============================================================================
// F: tiled SGEMM  f = tanh(read@Wf_r + Kf[q] + bf); p = sigmoid(f@Wp + bp)
//    grid = 256 (128 tokens each), block = 256, 8x8 thread tile.
//    Packed f32x2: a-operand DUPLICATED AT STAGING into rds2 (u64 = (r,r)),
//    b-pairs read directly as ulonglong2 from Wfs — zero packs in inner loop.
// ============================================================================
__global__ __launch_bounds__(256, 2)
void k_final(const int* __restrict__ q,
             const float* __restrict__ Wf,
             const float* __restrict__ bf,
             const float* __restrict__ Wp,
             const float* __restrict__ bp,
             float* __restrict__ out) {
    __shared__ __align__(16) float Wfs[DIM][DIM];             // 64 KB: [k][n]
    __shared__ __align__(16) unsigned long long rds2[128][17]; // dup read tile
    __shared__ float part[128][17];                           // partial p sums

    int tid = threadIdx.x;
    int ty = tid >> 4, tx = tid & 15;
    int tok0 = blockIdx.x * 128;

#pragma unroll
    for (int i = 0; i < 16; i++) {
        int idx = (tid + i * 256) * 4;
        *(float4*)&Wfs[idx >> 7][idx & 127] = *(const float4*)&Wf[idx];
    }
    __syncthreads();

    unsigned long long acc2[8][4];
#pragma unroll
    for (int i = 0; i < 8; i++)
#pragma unroll
        for (int j = 0; j < 4; j++) acc2[i][j] = 0ull;

    for (int kt = 0; kt < 8; kt++) {
        // stage read tile, duplicating each scalar into a (r,r) u64
#pragma unroll
        for (int v = 0; v < 2; v++) {
            int f = tid * 2 + v;              // 0..511 float4 ids
            int tok = f >> 2, dpos = (f & 3) * 4;
            float4 rv =
                *(const float4*)&g_read[(tok0 + tok) * DIM + kt * 16 + dpos];
            rds2[tok][dpos + 0] = pack2(rv.x, rv.x);
            rds2[tok][dpos + 1] = pack2(rv.y, rv.y);
            rds2[tok][dpos + 2] = pack2(rv.z, rv.z);
            rds2[tok][dpos + 3] = pack2(rv.w, rv.w);
        }
        __syncthreads();

#pragma unroll
        for (int kk = 0; kk < 16; kk++) {
            ulonglong2 b01 = *(const ulonglong2*)&Wfs[kt * 16 + kk][tx * 8];
            ulonglong2 b23 = *(const ulonglong2*)&Wfs[kt * 16 + kk][tx * 8 + 4];
#pragma unroll
            for (int i = 0; i < 8; i++) {
                unsigned long long a2 = rds2[ty * 8 + i][kk];
                fma2(acc2[i][0], a2, b01.x, acc2[i][0]);
                fma2(acc2[i][1], a2, b01.y, acc2[i][1]);
                fma2(acc2[i][2], a2, b23.x, acc2[i][2]);
                fma2(acc2[i][3], a2, b23.y, acc2[i][3]);
            }
        }
        __syncthreads();
    }

    // epilogue
    float4 bf0 = *(const float4*)&bf[tx * 8];
    float4 bf1 = *(const float4*)&bf[tx * 8 + 4];
    float bfv[8] = {bf0.x, bf0.y, bf0.z, bf0.w, bf1.x, bf1.y, bf1.z, bf1.w};
    float4 wp0 = *(const float4*)&Wp[tx * 8];
    float4 wp1 = *(const float4*)&Wp[tx * 8 + 4];
    float wpv[8] = {wp0.x, wp0.y, wp0.z, wp0.w, wp1.x, wp1.y, wp1.z, wp1.w};

    int qv[8];
#pragma unroll
    for (int i = 0; i < 8; i++) qv[i] = q[tok0 + ty * 8 + i];

#pragma unroll
    for (int i = 0; i < 8; i++) {
        const float* kf = g_Kf + qv[i] * DIM + tx * 8;
        float psum = 0.0f;
#pragma unroll
        for (int j = 0; j < 4; j++) {
            float lo, hi;
            unpack2(acc2[i][j], lo, hi);
            float f0 = tanhf(lo + kf[2 * j]     + bfv[2 * j]);
            float f1 = tanhf(hi + kf[2 * j + 1] + bfv[2 * j + 1]);
            psum = fmaf(f0, wpv[2 * j], psum);
            psum = fmaf(f1, wpv[2 * j + 1], psum);
        }
        part[ty * 8 + i][tx] = psum;
    }
    __syncthreads();

    if (tid < 128) {
        float s = 0.0f;
#pragma unroll
        for (int x = 0; x < 16; x++) s += part[tid][x];
        out[tok0 + tid] = 1.0f / (1.0f + expf(-(s + bp[0])));
    }
}

// ============================================================================
extern "C" void kernel_launch(void* const* d_in, const int* in_sizes, int n_in,
                              void* d_out, int out_size) {
    const int*   q   = (const int*)  d_in[0];
    const int*   r   = (const int*)  d_in[1];
    const float* Ek  = (const float*)d_in[2];
    const float* Ev  = (const float*)d_in[3];
    const float* Mk  = (const float*)d_in[4];
    const float* Mv0 = (const float*)d_in[5];
    const float* We  = (const float*)d_in[6];
    const float* be  = (const float*)d_in[7];
    const float* Wa  = (const float*)d_in[8];
    const float* ba  = (const float*)d_in[9];
    const float* Wf  = (const float*)d_in[10];
    const float* bf  = (const float*)d_in[11];
    const float* Wp  = (const float*)d_in[12];
    const float* bp  = (const float*)d_in[13];
    float* out = (float*)d_out;

    k_pre<<<375, 256>>>(Ev, We, be, Wa, ba, Ek, Mk, Wf);
    dim3 gs(2, BATCH);
    k_scan<<<gs, 256>>>(q, r, Mv0);
    k_final<<<BATCH * LEN / 128, 256>>>(q, Wf, bf, Wp, bp, out);
}

// round 7
// speedup vs baseline: 1.1924x; 1.1122x over previous
#include <cuda_runtime.h>
#include <cuda_bf16.h>
#include <mma.h>
#include <cstdint>

using namespace nvcuda;

#define NUM_C 1000
#define DIM 128
#define MSZ 64
#define BATCH 64
#define LEN 512

// ---------------- device scratch (static, no runtime alloc) ----------------
__device__ __align__(16) float g_W [NUM_C * MSZ];     // softmax(Ek@Mk^T) per q
__device__ __align__(16) float g_Ee[2 * NUM_C * DIM]; // sigmoid(Ev@We+be) per x
__device__ __align__(16) float g_Ea[2 * NUM_C * DIM]; // tanh(Ev@Wa+ba) per x
__device__ __align__(16) float g_Kf[NUM_C * DIM];     // Ek @ Wf[128:256,:]
__device__ __align__(16) float g_read0[BATCH * LEN * DIM]; // partial m 0..31
__device__ __align__(16) float g_read1[BATCH * LEN * DIM]; // partial m 32..63
// bf16 hi/lo images of B[n][k] = Wf[k][n] (plain [n][k] layout for wmma)
__device__ __align__(16) unsigned short g_Bhi16[DIM * DIM];
__device__ __align__(16) unsigned short g_Blo16[DIM * DIM];

// ---------------- packed f32x2 helpers (scan only) ----------------
__device__ __forceinline__ void fma2(unsigned long long& d,
                                     unsigned long long a,
                                     unsigned long long b,
                                     unsigned long long c) {
    asm("fma.rn.f32x2 %0, %1, %2, %3;" : "=l"(d) : "l"(a), "l"(b), "l"(c));
}
__device__ __forceinline__ unsigned long long pack2(float lo, float hi) {
    unsigned long long r;
    asm("mov.b64 %0, {%1, %2};" : "=l"(r) : "f"(lo), "f"(hi));
    return r;
}
__device__ __forceinline__ float sum2(unsigned long long v) {
    float lo, hi;
    asm("mov.b64 {%0, %1}, %2;" : "=f"(lo), "=f"(hi) : "l"(v));
    return lo + hi;
}

// ---------------- fast transcendentals ----------------
__device__ __forceinline__ float fast_tanh(float x) {
    float xc = fminf(fmaxf(x, -15.0f), 15.0f);
    float e = __expf(2.0f * xc);
    return __fdividef(e - 1.0f, e + 1.0f);
}
__device__ __forceinline__ float fast_sigmoid(float x) {
    float xc = fminf(fmaxf(x, -30.0f), 30.0f);
    return __frcp_rn(1.0f + __expf(-xc));
}

// ============================================================================
// P: fused precompute.  grid = 376, block = 256.
//    [0,250): erase/add tables; [250,375): softmax weights + Kf;
//    375: bf16 hi/lo [n][k] images of Wf_r for the wmma finale.
// ============================================================================
__global__ __launch_bounds__(256)
void k_pre(const float* __restrict__ Ev,
           const float* __restrict__ We, const float* __restrict__ be,
           const float* __restrict__ Wa, const float* __restrict__ ba,
           const float* __restrict__ Ek,
           const float* __restrict__ Mk,
           const float* __restrict__ Wf) {
    __shared__ float buf[12352];
    int t = threadIdx.x;

    if (blockIdx.x < 250) {
        // ---------------- erase/add branch: rows row0..row0+7 ----------------
        float (*vs)[DIM]  = (float (*)[DIM])buf;
        float (*pse)[DIM] = (float (*)[DIM])(buf + 1024);
        float (*psa)[DIM] = (float (*)[DIM])(buf + 2048);
        int row0 = blockIdx.x * 8;
#pragma unroll
        for (int k = 0; k < 4; k++) {
            int idx = t + k * 256;
            vs[idx >> 7][idx & 127] = Ev[row0 * DIM + idx];
        }
        __syncthreads();

        int col = t & 127, jh = t >> 7;
        int j0 = jh * 64;
        float ae[8] = {0,0,0,0,0,0,0,0};
        float aa[8] = {0,0,0,0,0,0,0,0};
#pragma unroll 4
        for (int jj = 0; jj < 64; jj++) {
            int j = j0 + jj;
            float we = We[j * DIM + col];
            float wa = Wa[j * DIM + col];
#pragma unroll
            for (int i = 0; i < 8; i++) {
                float v = vs[i][j];
                ae[i] = fmaf(v, we, ae[i]);
                aa[i] = fmaf(v, wa, aa[i]);
            }
        }
        if (jh == 0) {
#pragma unroll
            for (int i = 0; i < 8; i++) psa[i][col] = aa[i];
        } else {
#pragma unroll
            for (int i = 0; i < 8; i++) pse[i][col] = ae[i];
        }
        __syncthreads();
        if (jh == 0) {
            float bev = be[col];
#pragma unroll
            for (int i = 0; i < 8; i++)
                g_Ee[(row0 + i) * DIM + col] =
                    fast_sigmoid(ae[i] + pse[i][col] + bev);
        } else {
            float bav = ba[col];
#pragma unroll
            for (int i = 0; i < 8; i++)
                g_Ea[(row0 + i) * DIM + col] =
                    fast_tanh(aa[i] + psa[i][col] + bav);
        }
    } else if (blockIdx.x < 375) {
        // ---------------- w/Kf branch: rows row0..row0+7 ----------------
        float (*Mks)[129]    = (float (*)[129])buf;
        float (*krows)[DIM]  = (float (*)[DIM])(buf + 8256);
        float (*lgp)[8][MSZ] = (float (*)[8][MSZ])(buf + 9280);
        float (*lg)[MSZ]     = (float (*)[MSZ])(buf + 10816);
        float (*psk)[DIM]    = (float (*)[DIM])(buf + 11328);
        int row0 = (blockIdx.x - 250) * 8;
#pragma unroll
        for (int k = 0; k < 4; k++) {
            int idx = t + k * 256;
            krows[idx >> 7][idx & 127] = Ek[row0 * DIM + idx];
        }
#pragma unroll 8
        for (int k = 0; k < 32; k++) {
            int idx = t + k * 256;
            Mks[idx >> 7][idx & 127] = Mk[idx];
        }
        __syncthreads();

        int col = t & 127, jh = t >> 7;
        float ak[8] = {0,0,0,0,0,0,0,0};
#pragma unroll 4
        for (int jj = 0; jj < 64; jj++) {
            int j = jh * 64 + jj;
            float wf = Wf[(DIM + j) * DIM + col];
#pragma unroll
            for (int i = 0; i < 8; i++)
                ak[i] = fmaf(krows[i][j], wf, ak[i]);
        }
        if (jh == 1) {
#pragma unroll
            for (int i = 0; i < 8; i++) psk[i][col] = ak[i];
        }

        int m = t & 63, gh = t >> 6;
        float la[8] = {0,0,0,0,0,0,0,0};
#pragma unroll 4
        for (int jj = 0; jj < 32; jj++) {
            int j = gh * 32 + jj;
            float mk = Mks[m][j];
#pragma unroll
            for (int i = 0; i < 8; i++)
                la[i] = fmaf(krows[i][j], mk, la[i]);
        }
        if (gh > 0) {
#pragma unroll
            for (int i = 0; i < 8; i++) lgp[gh - 1][i][m] = la[i];
        }
        __syncthreads();

        if (jh == 0) {
#pragma unroll
            for (int i = 0; i < 8; i++)
                g_Kf[(row0 + i) * DIM + col] = ak[i] + psk[i][col];
        }
        if (gh == 0) {
#pragma unroll
            for (int i = 0; i < 8; i++)
                lg[i][m] = la[i] + lgp[0][i][m] + lgp[1][i][m] + lgp[2][i][m];
        }
        __syncthreads();

        int row = t >> 5, l = t & 31;
        float v0 = lg[row][l], v1 = lg[row][l + 32];
        float mx = fmaxf(v0, v1);
#pragma unroll
        for (int off = 1; off < 32; off <<= 1)
            mx = fmaxf(mx, __shfl_xor_sync(0xFFFFFFFFu, mx, off));
        float e0 = __expf(v0 - mx), e1 = __expf(v1 - mx);
        float s = e0 + e1;
#pragma unroll
        for (int off = 1; off < 32; off <<= 1)
            s += __shfl_xor_sync(0xFFFFFFFFu, s, off);
        float inv = __frcp_rn(s);
        g_W[(row0 + row) * MSZ + l]      = e0 * inv;
        g_W[(row0 + row) * MSZ + l + 32] = e1 * inv;
    } else {
        // ---------------- B image branch: bf16 hi/lo, [n][k] layout ---------
        for (int idx = t; idx < DIM * DIM; idx += 256) {
            int n = idx >> 7, k = idx & 127;
            float w = Wf[k * DIM + n];
            __nv_bfloat16 h = __float2bfloat16(w);
            __nv_bfloat16 l = __float2bfloat16(w - __bfloat162float(h));
            g_Bhi16[idx] = __bfloat16_as_ushort(h);
            g_Blo16[idx] = __bfloat16_as_ushort(l);
        }
    }
}

// ============================================================================
// S: sequential memory scan.  grid = (4, 64), block = 256.
//    blockIdx.x = dsplit (bit0) x msplit (bit1).  Each block: 64 d-cols,
//    32 memory slots.  Thread = (dl, mg): 8 m as 4 packed f32x2 regs.
//    Partial reads (sum over this block's 32 m) -> g_read0 / g_read1;
//    k_final sums the two partials.
// ============================================================================
__global__ __launch_bounds__(256)
void k_scan(const int* __restrict__ q, const int* __restrict__ r,
            const float* __restrict__ Mv0) {
    int b = blockIdx.y;
    int dsplit = blockIdx.x & 1;
    int msplit = blockIdx.x >> 1;
    int tid = threadIdx.x;
    int dl = tid >> 2;                 // 0..63
    int mg = tid & 3;                  // 0..3
    int d = dsplit * 64 + dl;
    int m0 = msplit * 32 + mg * 8;     // 8 m per thread

    __shared__ int sq[LEN];
    __shared__ int sx[LEN];
    __shared__ __align__(16) float sh_w[16][32];
    __shared__ float sh_e[16][64];
    __shared__ float sh_a[16][64];

    {
        const int* qb = q + b * LEN;
        const int* rb = r + b * LEN;
        for (int i = tid; i < LEN; i += 256) {
            int qv = qb[i];
            sq[i] = qv;
            sx[i] = qv + NUM_C * rb[i];
        }
    }

    unsigned long long Mv[4];
#pragma unroll
    for (int i = 0; i < 4; i++) {
        float lo = Mv0[(m0 + 2 * i) * DIM + d];
        float hi = Mv0[(m0 + 2 * i + 1) * DIM + d];
        Mv[i] = pack2(lo, hi);
    }
    __syncthreads();

    // staging: w 2/thread (16x32), e/a 4/thread (16x64)
    float rw[2], re[4], ra[4];
    int ws0[2], wm[2], es0[4], ed[4];
#pragma unroll
    for (int k = 0; k < 2; k++) {
        int idx = tid + k * 256;
        ws0[k] = idx >> 5; wm[k] = idx & 31;
    }
#pragma unroll
    for (int k = 0; k < 4; k++) {
        int idx = tid + k * 256;
        es0[k] = idx >> 6; ed[k] = (idx & 63) + dsplit * 64;
    }
#pragma unroll
    for (int k = 0; k < 2; k++)
        rw[k] = g_W[sq[ws0[k]] * MSZ + msplit * 32 + wm[k]];
#pragma unroll
    for (int k = 0; k < 4; k++) {
        re[k] = g_Ee[sx[es0[k]] * DIM + ed[k]];
        ra[k] = g_Ea[sx[es0[k]] * DIM + ed[k]];
    }

    float* gr = msplit ? g_read1 : g_read0;

    for (int c = 0; c < LEN / 16; c++) {
#pragma unroll
        for (int k = 0; k < 2; k++)
            sh_w[ws0[k]][wm[k]] = rw[k];
#pragma unroll
        for (int k = 0; k < 4; k++) {
            sh_e[es0[k]][ed[k] & 63] = re[k];
            sh_a[es0[k]][ed[k] & 63] = ra[k];
        }
        __syncthreads();

        if (c < LEN / 16 - 1) {
            int t1 = (c + 1) * 16;
#pragma unroll
            for (int k = 0; k < 2; k++)
                rw[k] = g_W[sq[t1 + ws0[k]] * MSZ + msplit * 32 + wm[k]];
#pragma unroll
            for (int k = 0; k < 4; k++) {
                re[k] = g_Ee[sx[t1 + es0[k]] * DIM + ed[k]];
                ra[k] = g_Ea[sx[t1 + es0[k]] * DIM + ed[k]];
            }
        }

        int t0 = c * 16;
#pragma unroll 4
        for (int s = 0; s < 16; s++) {
            float e = sh_e[s][dl];
            float a = sh_a[s][dl];
            unsigned long long ne2 = pack2(-e, -e);
            unsigned long long a2  = pack2(a, a);
            unsigned long long rd = 0ull;
            const unsigned long long* wrow =
                (const unsigned long long*)(&sh_w[s][mg * 8]);
#pragma unroll
            for (int i = 0; i < 4; i++) {
                unsigned long long w2 = wrow[i];
                unsigned long long tmp;
                fma2(rd, w2, Mv[i], rd);       // read += w * Mv_old
                fma2(tmp, ne2, Mv[i], a2);     // tmp = a - e*Mv
                fma2(Mv[i], w2, tmp, Mv[i]);   // Mv += w*tmp
            }
            float rs = sum2(rd);
            rs += __shfl_xor_sync(0xFFFFFFFFu, rs, 1);
            rs += __shfl_xor_sync(0xFFFFFFFFu, rs, 2);
            if (mg == 0)
                gr[(b * LEN + t0 + s) * DIM + d] = rs;
        }
        __syncthreads();
    }
}

// ============================================================================
// F: wmma bf16 split-precision finale.
//    grid = 128 (16 tokens each), block = 128 (4 warps; warp w covers n-cols
//    [32w, 32w+32)).  A = read (partials summed), split hi/lo bf16.
//    B = Wf_r hi/lo [n][k] images -> smem, wmma col_major.
//    3 passes: Ahi*Bhi + Ahi*Blo + Alo*Bhi, fp32 accumulators.
//    Epilogue: f = tanh(D + Kf[q] + bf); p = sigmoid(f . Wp + bp).
// ============================================================================
#define FPAD 144
#define SA_HI 0
#define SA_LO 4608
#define SB_HI 9216
#define SB_LO 46080
#define SD    82944
#define SMF_TOTAL 92160

__global__ __launch_bounds__(128)
void k_final(const int* __restrict__ q,
             const float* __restrict__ bfp,
             const float* __restrict__ Wp,
             const float* __restrict__ bp,
             float* __restrict__ out) {
    extern __shared__ char smem[];
    __nv_bfloat16* Ahi = (__nv_bfloat16*)(smem + SA_HI);
    __nv_bfloat16* Alo = (__nv_bfloat16*)(smem + SA_LO);
    __nv_bfloat16* Bhi = (__nv_bfloat16*)(smem + SB_HI);
    __nv_bfloat16* Blo = (__nv_bfloat16*)(smem + SB_LO);
    float* D = (float*)(smem + SD);
    int tid = threadIdx.x;
    int tok0 = blockIdx.x * 16;

    // stage B hi/lo (coalesced uint4)
    const uint4* srcH = (const uint4*)g_Bhi16;
    const uint4* srcL = (const uint4*)g_Blo16;
#pragma unroll
    for (int i = 0; i < 16; i++) {
        int id = tid + i * 128;        // 2048 uint4 total
        int row = id >> 4, c = id & 15;
        *(uint4*)(Bhi + row * FPAD + c * 8) = srcH[id];
        *(uint4*)(Blo + row * FPAD + c * 8) = srcL[id];
    }
    // stage A: sum partial reads, split hi/lo
    {
        int tok = tid >> 3, seg = tid & 7;
        const float4* p0 = (const float4*)(g_read0 +
                           (size_t)(tok0 + tok) * DIM + seg * 16);
        const float4* p1 = (const float4*)(g_read1 +
                           (size_t)(tok0 + tok) * DIM + seg * 16);
#pragma unroll
        for (int v = 0; v < 4; v++) {
            float4 x0 = p0[v];
            float4 x1 = p1[v];
            float xs[4] = {x0.x + x1.x, x0.y + x1.y, x0.z + x1.z, x0.w + x1.w};
#pragma unroll
            for (int e = 0; e < 4; e++) {
                int k = seg * 16 + v * 4 + e;
                float w = xs[e];
                __nv_bfloat16 h = __float2bfloat16(w);
                __nv_bfloat16 l = __float2bfloat16(w - __bfloat162float(h));
                Ahi[tok * FPAD + k] = h;
                Alo[tok * FPAD + k] = l;
            }
        }
    }
    __syncthreads();

    int wid = tid >> 5;
    int n0 = wid * 32;
    wmma::fragment<wmma::matrix_a, 16, 16, 16, __nv_bfloat16,
                   wmma::row_major> af;
    wmma::fragment<wmma::matrix_b, 16, 16, 16, __nv_bfloat16,
                   wmma::col_major> bfr;
    wmma::fragment<wmma::accumulator, 16, 16, 16, float> acc0, acc1;
    wmma::fill_fragment(acc0, 0.0f);
    wmma::fill_fragment(acc1, 0.0f);
#pragma unroll
    for (int pass = 0; pass < 3; pass++) {
        const __nv_bfloat16* A = (pass == 2) ? Alo : Ahi;
        const __nv_bfloat16* B = (pass == 1) ? Blo : Bhi;
#pragma unroll
        for (int ks = 0; ks < 8; ks++) {
            wmma::load_matrix_sync(af, A + ks * 16, FPAD);
            wmma::load_matrix_sync(bfr, B + n0 * FPAD + ks * 16, FPAD);
            wmma::mma_sync(acc0, af, bfr, acc0);
            wmma::load_matrix_sync(bfr, B + (n0 + 16) * FPAD + ks * 16, FPAD);
            wmma::mma_sync(acc1, af, bfr, acc1);
        }
    }
    wmma::store_matrix_sync(D + n0, acc0, FPAD, wmma::mem_row_major);
    wmma::store_matrix_sync(D + n0 + 16, acc1, FPAD, wmma::mem_row_major);
    __syncthreads();

    // epilogue: 8 threads per token, 16 n each, shfl-reduce
    int tok = tid >> 3, g = tid & 7;
    int qv = q[tok0 + tok];
    const float* kfr = g_Kf + qv * DIM + g * 16;
    const float* drow = D + tok * FPAD + g * 16;
    float psum = 0.0f;
#pragma unroll
    for (int j = 0; j < 16; j++) {
        float f = fast_tanh(drow[j] + kfr[j] + bfp[g * 16 + j]);
        psum = fmaf(f, Wp[g * 16 + j], psum);
    }
    psum += __shfl_xor_sync(0xFFFFFFFFu, psum, 1);
    psum += __shfl_xor_sync(0xFFFFFFFFu, psum, 2);
    psum += __shfl_xor_sync(0xFFFFFFFFu, psum, 4);
    if (g == 0) out[tok0 + tok] = fast_sigmoid(psum + bp[0]);
}

// ============================================================================
extern "C" void kernel_launch(void* const* d_in, const int* in_sizes, int n_in,
                              void* d_out, int out_size) {
    const int*   q   = (const int*)  d_in[0];
    const int*   r   = (const int*)  d_in[1];
    const float* Ek  = (const float*)d_in[2];
    const float* Ev  = (const float*)d_in[3];
    const float* Mk  = (const float*)d_in[4];
    const float* Mv0 = (const float*)d_in[5];
    const float* We  = (const float*)d_in[6];
    const float* be  = (const float*)d_in[7];
    const float* Wa  = (const float*)d_in[8];
    const float* ba  = (const float*)d_in[9];
    const float* Wf  = (const float*)d_in[10];
    const float* bf  = (const float*)d_in[11];
    const float* Wp  = (const float*)d_in[12];
    const float* bp  = (const float*)d_in[13];
    float* out = (float*)d_out;

    static int smem_set = 0;
    if (!smem_set) {
        cudaFuncSetAttribute(k_final,
                             cudaFuncAttributeMaxDynamicSharedMemorySize,
                             SMF_TOTAL);
        smem_set = 1;
    }

    k_pre<<<376, 256>>>(Ev, We, be, Wa, ba, Ek, Mk, Wf);
    dim3 gs(4, BATCH);
    k_scan<<<gs, 256>>>(q, r, Mv0);
    k_final<<<BATCH * LEN / 16, 128, SMF_TOTAL>>>(q, bf, Wp, bp, out);
}